// round 3
// baseline (speedup 1.0000x reference)
#include <cuda_runtime.h>
#include <math.h>

// loss_concentration: per-slice unbiased variance over [H,W]=240x320, summed
// over [B,K]=16x64, then sqrt. Input: 78,643,200 fp32 (314.6 MB). Output: 1 fp32.
// Pure HBM-streaming problem; roofline floor ~50 us at ~6.5 TB/s effective.

#define SLICE_ELEMS   (240 * 320)      // 76800
#define SLICE_VEC4    (SLICE_ELEMS/4)  // 19200
#define NUM_SLICES    (16 * 64)        // 1024
#define THREADS       256

// Per-slice variance scratch (device global: allocation-free, graph-safe).
// Every slot is unconditionally overwritten each launch -> replay-deterministic.
__device__ float g_slice_var[NUM_SLICES];

__global__ __launch_bounds__(THREADS) void slice_var_kernel(const float* __restrict__ x) {
    const int slice = blockIdx.x;
    const float4* __restrict__ p =
        reinterpret_cast<const float4*>(x + (size_t)slice * SLICE_ELEMS);

    float s  = 0.0f;   // sum
    float ss = 0.0f;   // sum of squares

    // 19200 float4 / 256 threads = 75 iterations per thread.
    // Unroll 15 (divides 75) to front-batch independent LDG.128s -> high MLP,
    // DRAM latency fully hidden. __ldcs: streamed-once data, evict-first.
    #pragma unroll 15
    for (int i = threadIdx.x; i < SLICE_VEC4; i += THREADS) {
        float4 v = __ldcs(p + i);
        s  += (v.x + v.y) + (v.z + v.w);
        ss += (v.x * v.x + v.y * v.y) + (v.z * v.z + v.w * v.w);
    }

    // Warp reduction
    #pragma unroll
    for (int o = 16; o > 0; o >>= 1) {
        s  += __shfl_xor_sync(0xFFFFFFFFu, s,  o);
        ss += __shfl_xor_sync(0xFFFFFFFFu, ss, o);
    }

    __shared__ float sh_s[THREADS / 32];
    __shared__ float sh_ss[THREADS / 32];
    const int warp = threadIdx.x >> 5;
    const int lane = threadIdx.x & 31;
    if (lane == 0) {
        sh_s[warp]  = s;
        sh_ss[warp] = ss;
    }
    __syncthreads();

    if (threadIdx.x == 0) {
        float S = 0.0f, SS = 0.0f;
        #pragma unroll
        for (int w = 0; w < THREADS / 32; w++) {
            S  += sh_s[w];
            SS += sh_ss[w];
        }
        const float n = (float)SLICE_ELEMS;
        // unbiased (ddof=1) variance
        g_slice_var[slice] = (SS - S * S / n) / (n - 1.0f);
    }
}

// Sum 1024 per-slice variances and take sqrt. One 256-thread block.
__global__ __launch_bounds__(THREADS) void finish_kernel(float* __restrict__ out) {
    float acc = 0.0f;
    #pragma unroll 4
    for (int i = threadIdx.x; i < NUM_SLICES; i += THREADS)
        acc += g_slice_var[i];

    #pragma unroll
    for (int o = 16; o > 0; o >>= 1)
        acc += __shfl_xor_sync(0xFFFFFFFFu, acc, o);

    __shared__ float sh[THREADS / 32];
    const int warp = threadIdx.x >> 5;
    const int lane = threadIdx.x & 31;
    if (lane == 0) sh[warp] = acc;
    __syncthreads();

    if (threadIdx.x == 0) {
        float total = 0.0f;
        #pragma unroll
        for (int w = 0; w < THREADS / 32; w++) total += sh[w];
        out[0] = sqrtf(total);
    }
}

extern "C" void kernel_launch(void* const* d_in, const int* in_sizes, int n_in,
                              void* d_out, int out_size) {
    const float* softmask = (const float*)d_in[0];
    float* out = (float*)d_out;

    slice_var_kernel<<<NUM_SLICES, THREADS>>>(softmask);
    finish_kernel<<<1, THREADS>>>(out);
}